// round 9
// baseline (speedup 1.0000x reference)
#include <cuda_runtime.h>
#include <cuda_bf16.h>
#include <math.h>
#include <cstdint>
#include <cstddef>

typedef __nv_bfloat16 bf16;

#define MROWS 32768
#define HD    512
#define WSZ   (512*512)
#define RSTRIDE 1024            // interleaved row stride in bf16 elems (hi+lo)
#define WELEMS  ((size_t)HD * RSTRIDE)

#define BM 128
#define BN 128
#define NTH 256
#define NTILES_PER_STAGE 1024   // 4 n-blocks x 256 m-blocks
#define NTILES_TOTAL     4096
#define PGRID 304               // 2 CTAs/SM x 152 SMs

// smem: 1024 B header (bias) + 3 stages x 32 KB (A 16K + W 16K)
#define A_OFF  0u
#define W_OFF  16384u
#define STAGE  32768u
#define NSTAGE 3
#define SMEMB  (1024u + NSTAGE*STAGE)   // 99328

// ------------- scratch (static device arrays, no runtime alloc) -------------
__device__ bf16  g_Xhl [(size_t)MROWS * RSTRIDE];
__device__ bf16  g_H0hl[(size_t)MROWS * RSTRIDE];
__device__ bf16  g_H1hl[(size_t)MROWS * RSTRIDE];
__device__ bf16  g_Whl [4 * WELEMS];
__device__ float g_beff[2 * HD];
__device__ int   g_sync[1 + 3 * 256];   // [0]=tile counter, rest: done[stage][mb]

// ----------------------------- PTX helpers ----------------------------------
__device__ __forceinline__ uint32_t s2u(const void* p) {
    uint32_t a;
    asm("{ .reg .u64 t; cvta.to.shared.u64 t, %1; cvt.u32.u64 %0, t; }" : "=r"(a) : "l"(p));
    return a;
}
__device__ __forceinline__ void cp16(uint32_t dst, const void* src) {
    asm volatile("cp.async.cg.shared.global [%0], [%1], 16;" :: "r"(dst), "l"(src));
}
#define CP_COMMIT() asm volatile("cp.async.commit_group;" ::: "memory")

__device__ __forceinline__ void ldsm4(uint32_t& r0, uint32_t& r1, uint32_t& r2,
                                      uint32_t& r3, uint32_t addr) {
    asm volatile("ldmatrix.sync.aligned.m8n8.x4.shared.b16 {%0,%1,%2,%3}, [%4];"
                 : "=r"(r0), "=r"(r1), "=r"(r2), "=r"(r3) : "r"(addr));
}
__device__ __forceinline__ void mma16816(float* c, const uint32_t* a, const uint32_t* b) {
    asm volatile(
        "mma.sync.aligned.m16n8k16.row.col.f32.bf16.bf16.f32 "
        "{%0,%1,%2,%3}, {%4,%5,%6,%7}, {%8,%9}, {%0,%1,%2,%3};"
        : "+f"(c[0]), "+f"(c[1]), "+f"(c[2]), "+f"(c[3])
        : "r"(a[0]), "r"(a[1]), "r"(a[2]), "r"(a[3]), "r"(b[0]), "r"(b[1]));
}

// fast accurate tanh: 1 - 2/(exp(2x)+1)
__device__ __forceinline__ float tfast(float x) {
    float e, r;
    asm("ex2.approx.f32 %0, %1;" : "=f"(e) : "f"(x * 2.8853900817779268f));
    asm("rcp.approx.f32 %0, %1;" : "=f"(r) : "f"(e + 1.0f));
    return fmaf(-2.0f, r, 1.0f);
}

__device__ __forceinline__ void split2(float x, bf16& h, bf16& l) {
    h = __float2bfloat16_rn(x);
    l = __float2bfloat16_rn(x - __bfloat162float(h));
}

// ------------------------- persistent GEMM kernel ----------------------------
// 4 chained stages, tiles pulled from a global counter; stage s>=1 tile (m, n)
// waits until all 4 n-tiles of stage s-1 row-block m have been published.
struct PP {
    const bf16*  A[4];
    const bf16*  W[4];
    const float* b0[4];
    const float* b1[4];
    bf16*        outHL[3];   // stages 0..2
    float*       outF;       // stage 3
    float*       hsf;        // stage 2 extra
};

__global__ void __launch_bounds__(NTH, 2) gemm_persist(PP p)
{
    extern __shared__ char smem[];
    __shared__ int s_tile;
    const uint32_t sb = s2u(smem);
    const int t   = threadIdx.x;
    const int wid = t >> 5;
    const int lid = t & 31;
    const int wm  = wid & 3;       // 0..3 (M, 32 rows)
    const int wn  = wid >> 2;      // 0..1 (N, 64 cols)

    // ldmatrix per-lane addressing (scheme verified R4+)
    const int q   = lid >> 3;
    const int lr8 = lid & 7;
    const int sws = lr8;
    const uint32_t aOff = (uint32_t)((wm * 32 + (q & 1) * 8 + lr8) * 128);
    const int aHalf = q >> 1;
    const uint32_t bOff = (uint32_t)((wn * 64 + (q >> 1) * 8 + lr8) * 128);
    const int bHalf = q & 1;
    const int lq = lid >> 2;
    const int lr = lid & 3;

#pragma unroll 1
    for (;;) {
        if (t == 0) s_tile = atomicAdd(&g_sync[0], 1);
        __syncthreads();
        const int tile = s_tile;
        if (tile >= NTILES_TOTAL) return;

        const int stage = tile >> 10;
        const int rem   = tile & 1023;
        const int mb    = rem >> 2;
        const int nb    = rem & 3;
        const int m0    = mb * BM;
        const int n0    = nb * BN;

        // ---- dependency wait (stages 1..3 consume previous stage's rows) ----
        if (stage > 0) {
            if (t == 0) {
                const int* fp = &g_sync[1 + (stage - 1) * 256 + mb];
                int v;
                for (;;) {
                    asm volatile("ld.acquire.gpu.global.b32 %0, [%1];"
                                 : "=r"(v) : "l"(fp) : "memory");
                    if (v >= 4) break;
                    __nanosleep(64);
                }
            }
            __syncthreads();
        }

        const bf16* __restrict__ A0 = p.A[stage];
        const bf16* __restrict__ W0 = p.W[stage];

        // bias -> smem header
        if (t < BN) {
            float b = p.b0[stage][n0 + t];
            if (p.b1[stage]) b += p.b1[stage][n0 + t];
            ((float*)smem)[t] = b;
        }

        float acc[2][8][4];
#pragma unroll
        for (int mt = 0; mt < 2; ++mt)
#pragma unroll
            for (int nt = 0; nt < 8; ++nt)
#pragma unroll
                for (int e = 0; e < 4; ++e) acc[mt][nt][e] = 0.0f;

        const int NC = 16;   // KC=32 chunks over K=512

        auto load_chunk = [&](int cc) {
            const int kc = cc;
            const uint32_t st = sb + 1024 + (uint32_t)(cc % NSTAGE) * STAGE;
#pragma unroll
            for (int i = 0; i < 4; ++i) {             // A: 128 rows x 8 c16
                int idx = t + i * NTH;
                int r = idx >> 3, c = idx & 7;
                uint32_t d = st + A_OFF + r * 128 + (uint32_t)((c ^ (r & 7)) << 4);
                cp16(d, A0 + (size_t)(m0 + r) * RSTRIDE + kc * 64 + c * 8);
            }
#pragma unroll
            for (int i = 0; i < 4; ++i) {             // W: 128 rows x 8 c16
                int idx = t + i * NTH;
                int r = idx >> 3, c = idx & 7;
                uint32_t d = st + W_OFF + r * 128 + (uint32_t)((c ^ (r & 7)) << 4);
                cp16(d, W0 + (size_t)(n0 + r) * RSTRIDE + kc * 64 + c * 8);
            }
            CP_COMMIT();
        };

        load_chunk(0);
        load_chunk(1);

#pragma unroll 1
        for (int cc = 0; cc < NC; ++cc) {
            if (cc < NC - 1) asm volatile("cp.async.wait_group 1;" ::: "memory");
            else             asm volatile("cp.async.wait_group 0;" ::: "memory");
            __syncthreads();
            if (cc + 2 < NC) load_chunk(cc + 2);

            const uint32_t st = sb + 1024 + (uint32_t)(cc % NSTAGE) * STAGE;
            const uint32_t aB = st + A_OFF + aOff;
            const uint32_t bB = st + W_OFF + bOff;

#pragma unroll
            for (int ks = 0; ks < 2; ++ks) {
                const uint32_t caH = (uint32_t)(((2 * ks + aHalf) ^ sws) << 4);
                const uint32_t caL = (uint32_t)(((4 + 2 * ks + aHalf) ^ sws) << 4);
                const uint32_t cbH = (uint32_t)(((2 * ks + bHalf) ^ sws) << 4);
                const uint32_t cbL = (uint32_t)(((4 + 2 * ks + bHalf) ^ sws) << 4);
                uint32_t a[2][4], b[8][2];

                // A_hi
#pragma unroll
                for (int mt = 0; mt < 2; ++mt)
                    ldsm4(a[mt][0], a[mt][1], a[mt][2], a[mt][3],
                          aB + mt * 2048 + caH);
                // W_lo -> acc += Ah*Wl
#pragma unroll
                for (int bt = 0; bt < 4; ++bt)
                    ldsm4(b[2*bt][0], b[2*bt][1], b[2*bt+1][0], b[2*bt+1][1],
                          bB + bt * 2048 + cbL);
#pragma unroll
                for (int mt = 0; mt < 2; ++mt)
#pragma unroll
                    for (int nt = 0; nt < 8; ++nt)
                        mma16816(acc[mt][nt], a[mt], b[nt]);
                // W_hi -> acc += Ah*Wh
#pragma unroll
                for (int bt = 0; bt < 4; ++bt)
                    ldsm4(b[2*bt][0], b[2*bt][1], b[2*bt+1][0], b[2*bt+1][1],
                          bB + bt * 2048 + cbH);
#pragma unroll
                for (int mt = 0; mt < 2; ++mt)
#pragma unroll
                    for (int nt = 0; nt < 8; ++nt)
                        mma16816(acc[mt][nt], a[mt], b[nt]);
                // A_lo -> acc += Al*Wh
#pragma unroll
                for (int mt = 0; mt < 2; ++mt)
                    ldsm4(a[mt][0], a[mt][1], a[mt][2], a[mt][3],
                          aB + mt * 2048 + caL);
#pragma unroll
                for (int mt = 0; mt < 2; ++mt)
#pragma unroll
                    for (int nt = 0; nt < 8; ++nt)
                        mma16816(acc[mt][nt], a[mt], b[nt]);
            }
        }

        // ------------------------------ epilogue -----------------------------
        const bool do_tanh = (stage < 3);
        const bool do_hsf  = (stage == 2);
        const bool do_trans = (stage == 3);
        const float* bsm = (const float*)smem;
        bf16*  oHL = (stage < 3) ? p.outHL[stage] : nullptr;

#pragma unroll
        for (int mt = 0; mt < 2; ++mt) {
#pragma unroll
            for (int hf = 0; hf < 2; ++hf) {
                const int m = m0 + wm * 32 + mt * 16 + lq + hf * 8;
#pragma unroll
                for (int nt = 0; nt < 8; ++nt) {
                    const int n = n0 + wn * 64 + nt * 8 + lr * 2;
                    float x0 = acc[mt][nt][hf * 2 + 0] + bsm[n - n0];
                    float x1 = acc[mt][nt][hf * 2 + 1] + bsm[n - n0 + 1];
                    if (do_tanh) { x0 = tfast(x0); x1 = tfast(x1); }

                    if (do_trans) {
                        const int s = m & 4095, bb = m >> 12;
                        float* dst = p.outF + ((size_t)(s * 8 + bb)) * HD + n;
                        *(float2*)dst = make_float2(x0, x1);
                    } else {
                        __nv_bfloat162 hh, ll;
                        split2(x0, hh.x, ll.x);
                        split2(x1, hh.y, ll.y);
                        bf16* base = oHL + (size_t)m * RSTRIDE + (n >> 5) * 64;
                        const int w = n & 31;
                        *(__nv_bfloat162*)(base + w)      = hh;
                        *(__nv_bfloat162*)(base + 32 + w) = ll;
                    }
                    if (do_hsf && ((m & 4095) == 4095)) {
                        float* hd = p.hsf + (size_t)(m >> 12) * HD + n;
                        *(float2*)hd = make_float2(x0, x1);
                    }
                }
            }
        }

        // ---- publish completion ----
        if (stage < 3) {
            __threadfence();
            __syncthreads();
            if (t == 0) atomicAdd(&g_sync[1 + stage * 256 + mb], 1);
        } else {
            __syncthreads();
        }
    }
}

// ------------------------------- prep kernels -------------------------------
__global__ void k_zero()
{
    int i = blockIdx.x * blockDim.x + threadIdx.x;
    if (i < 1 + 3 * 256) g_sync[i] = 0;
}

// Weff = Whh + Wxh @ Why, written DIRECTLY in hi/lo-interleaved bf16 layout.
struct WeffP {
    const float* A[2];     // Wxh  [n][j]
    const float* B[2];     // Why  [j][k]
    const float* Wadd[2];  // Whh  [n][k]
    bf16*        C[2];     // interleaved dst (g_Whl slot)
};

__global__ void __launch_bounds__(256) k_weff(WeffP wp)
{
    const int l = blockIdx.z;
    const float* __restrict__ A = wp.A[l];
    const float* __restrict__ B = wp.B[l];
    const float* __restrict__ Wadd = wp.Wadd[l];
    bf16* __restrict__ C = wp.C[l];

    __shared__ float As[16][64];
    __shared__ float Bs[16][64];
    const int t  = threadIdx.x;
    const int tx = t & 15, ty = t >> 4;
    const int m0 = blockIdx.y * 64, n0 = blockIdx.x * 64;

    float acc[4][4] = {};
#pragma unroll 1
    for (int kt = 0; kt < 512; kt += 16) {
#pragma unroll
        for (int e = t; e < 1024; e += 256) {
            int am = e >> 4, ak = e & 15;
            As[ak][am] = A[(size_t)(m0 + am) * 512 + kt + ak];
            int bj = e & 63, bk = e >> 6;
            Bs[bk][bj] = B[(size_t)(kt + bk) * 512 + n0 + bj];
        }
        __syncthreads();
#pragma unroll
        for (int k = 0; k < 16; ++k) {
            float af[4], bf[4];
#pragma unroll
            for (int i = 0; i < 4; ++i) af[i] = As[k][ty * 4 + i];
#pragma unroll
            for (int j = 0; j < 4; ++j) bf[j] = Bs[k][tx * 4 + j];
#pragma unroll
            for (int i = 0; i < 4; ++i)
#pragma unroll
                for (int j = 0; j < 4; ++j)
                    acc[i][j] = fmaf(af[i], bf[j], acc[i][j]);
        }
        __syncthreads();
    }

    const int kcol = n0 + tx * 4;
#pragma unroll
    for (int i = 0; i < 4; ++i) {
        const int n = m0 + ty * 4 + i;
        bf16 h[4], lo[4];
#pragma unroll
        for (int j = 0; j < 4; ++j) {
            float v = Wadd[(size_t)n * 512 + kcol + j] + acc[i][j];
            split2(v, h[j], lo[j]);
        }
        bf16* base = C + (size_t)n * RSTRIDE + (kcol >> 5) * 64 + (kcol & 31);
        *(uint2*)base        = *(uint2*)h;
        *(uint2*)(base + 32) = *(uint2*)lo;
    }
}

// beff = bhh + bxh + Wxh @ bhy : one warp per output element
struct BeffP {
    const float* Wxh[2];
    const float* bhh[2];
    const float* bxh[2];
    const float* bhy[2];
    float*       out[2];
};

__global__ void k_beff(BeffP bp)
{
    const int gw = (blockIdx.x * blockDim.x + threadIdx.x) >> 5;
    const int l = gw >> 9;
    const int n = gw & 511;
    const int lane = threadIdx.x & 31;
    const float* W  = bp.Wxh[l] + (size_t)n * 512 + lane * 16;
    const float* bh = bp.bhy[l] + lane * 16;
    float s = 0.0f;
#pragma unroll
    for (int k = 0; k < 16; k += 4) {
        float4 w = *(const float4*)(W + k);
        float4 b = *(const float4*)(bh + k);
        s = fmaf(w.x, b.x, s); s = fmaf(w.y, b.y, s);
        s = fmaf(w.z, b.z, s); s = fmaf(w.w, b.w, s);
    }
#pragma unroll
    for (int o = 16; o; o >>= 1) s += __shfl_xor_sync(0xFFFFFFFFu, s, o);
    if (lane == 0) bp.out[l][n] = bp.bhh[l][n] + bp.bxh[l][n] + s;
}

// hi/lo interleaved splits
__global__ void k_split_x(const float* __restrict__ x, bf16* __restrict__ dst)
{
    const size_t idx = (size_t)blockIdx.x * blockDim.x + threadIdx.x;
    const size_t row = idx >> 4;
    const int    kc  = (int)(idx & 15);
    const float* src = x + row * 512 + kc * 32;
    bf16* d = dst + row * RSTRIDE + kc * 64;

    uint32_t hi[16], lo[16];
#pragma unroll
    for (int j = 0; j < 8; ++j) {
        float4 v = *(const float4*)(src + j * 4);
        __nv_bfloat162 h0, l0, h1, l1;
        split2(v.x, h0.x, l0.x); split2(v.y, h0.y, l0.y);
        split2(v.z, h1.x, l1.x); split2(v.w, h1.y, l1.y);
        hi[2*j]   = *(uint32_t*)&h0; hi[2*j+1] = *(uint32_t*)&h1;
        lo[2*j]   = *(uint32_t*)&l0; lo[2*j+1] = *(uint32_t*)&l1;
    }
#pragma unroll
    for (int j = 0; j < 4; ++j) {
        ((uint4*)d)[j]      = *(uint4*)(hi + 4*j);
        ((uint4*)(d+32))[j] = *(uint4*)(lo + 4*j);
    }
}

struct WPtrs { const float* p[2]; };

__global__ void k_split_w(WPtrs wp, bf16* __restrict__ dst)
{
    const size_t idx = (size_t)blockIdx.x * blockDim.x + threadIdx.x;
    const int slot = (int)(idx >> 13);             // 0 or 1
    const size_t row = (idx >> 4) & 511;
    const int    kc  = (int)(idx & 15);
    const float* src = wp.p[slot] + row * 512 + kc * 32;
    // slot 0 -> Whl slot 0 (W_xh0), slot 1 -> Whl slot 3 (final projection)
    bf16* d = dst + (size_t)(slot * 3) * WELEMS + row * RSTRIDE + kc * 64;

    uint32_t hi[16], lo[16];
#pragma unroll
    for (int j = 0; j < 8; ++j) {
        float4 v = *(const float4*)(src + j * 4);
        __nv_bfloat162 h0, l0, h1, l1;
        split2(v.x, h0.x, l0.x); split2(v.y, h0.y, l0.y);
        split2(v.z, h1.x, l1.x); split2(v.w, h1.y, l1.y);
        hi[2*j]   = *(uint32_t*)&h0; hi[2*j+1] = *(uint32_t*)&h1;
        lo[2*j]   = *(uint32_t*)&l0; lo[2*j+1] = *(uint32_t*)&l1;
    }
#pragma unroll
    for (int j = 0; j < 4; ++j) {
        ((uint4*)d)[j]      = *(uint4*)(hi + 4*j);
        ((uint4*)(d+32))[j] = *(uint4*)(lo + 4*j);
    }
}

// --------------------------------- launcher ---------------------------------
extern "C" void kernel_launch(void* const* d_in, const int* in_sizes, int n_in,
                              void* d_out, int out_size)
{
    const float* xs     = (const float*)d_in[0];
    const float* W_xh0  = (const float*)d_in[1];
    const float* b_xh0  = (const float*)d_in[2];
    const float* b_hh0  = (const float*)d_in[4];
    const float* W_hy0  = (const float*)d_in[5];
    const float* b_hy0  = (const float*)d_in[6];
    const float* W_xh_h = (const float*)d_in[7];
    const float* b_xh_h = (const float*)d_in[8];
    const float* W_hh_h = (const float*)d_in[9];
    const float* b_hh_h = (const float*)d_in[10];
    const float* W_hy_h = (const float*)d_in[11];
    const float* b_hy_h = (const float*)d_in[12];

    float* out = (float*)d_out;
    float* hs_final = out + (size_t)4096 * 8 * HD;

    bf16 *Xhl, *H0hl, *H1hl, *Whl;
    float *beff;
    cudaGetSymbolAddress((void**)&Xhl,  g_Xhl);
    cudaGetSymbolAddress((void**)&H0hl, g_H0hl);
    cudaGetSymbolAddress((void**)&H1hl, g_H1hl);
    cudaGetSymbolAddress((void**)&Whl,  g_Whl);
    cudaGetSymbolAddress((void**)&beff, g_beff);

    cudaFuncSetAttribute(gemm_persist,
                         cudaFuncAttributeMaxDynamicSharedMemorySize, SMEMB);

#define WS(s) (Whl + (size_t)(s) * WELEMS)

    // ---- prep ----
    k_zero<<<4, 256>>>();

    WeffP wep;
    wep.A[0] = W_xh_h;        wep.A[1] = W_xh_h + WSZ;
    wep.B[0] = W_hy0;         wep.B[1] = W_hy_h;
    wep.Wadd[0] = W_hh_h;     wep.Wadd[1] = W_hh_h + WSZ;
    wep.C[0] = WS(1);         wep.C[1] = WS(2);
    k_weff<<<dim3(8, 8, 2), 256>>>(wep);

    BeffP bep;
    bep.Wxh[0] = W_xh_h;      bep.Wxh[1] = W_xh_h + WSZ;
    bep.bhh[0] = b_hh_h;      bep.bhh[1] = b_hh_h + HD;
    bep.bxh[0] = b_xh_h;      bep.bxh[1] = b_xh_h + HD;
    bep.bhy[0] = b_hy0;       bep.bhy[1] = b_hy_h;
    bep.out[0] = beff;        bep.out[1] = beff + HD;
    k_beff<<<128, 256>>>(bep);

    k_split_x<<<2048, 256>>>(xs, Xhl);
    WPtrs wp;
    wp.p[0] = W_xh0;
    wp.p[1] = W_hy_h + WSZ;
    k_split_w<<<64, 256>>>(wp, Whl);

    // ---- persistent 4-stage GEMM chain ----
    PP p;
    p.A[0] = Xhl;   p.A[1] = H0hl;  p.A[2] = H1hl;  p.A[3] = H0hl;
    p.W[0] = WS(0); p.W[1] = WS(1); p.W[2] = WS(2); p.W[3] = WS(3);
    p.b0[0] = b_xh0;       p.b1[0] = b_hh0;
    p.b0[1] = beff;        p.b1[1] = nullptr;
    p.b0[2] = beff + HD;   p.b1[2] = nullptr;
    p.b0[3] = b_hy_h + HD; p.b1[3] = nullptr;
    p.outHL[0] = H0hl;  p.outHL[1] = H1hl;  p.outHL[2] = H0hl;
    p.outF = out;
    p.hsf  = hs_final;

    gemm_persist<<<PGRID, NTH, SMEMB>>>(p);
#undef WS
}

// round 10
// speedup vs baseline: 1.2056x; 1.2056x over previous
#include <cuda_runtime.h>
#include <cuda_bf16.h>
#include <math.h>
#include <cstdint>
#include <cstddef>

typedef __nv_bfloat16 bf16;

#define MROWS 32768
#define HD    512
#define WSZ   (512*512)
#define RSTRIDE 1024            // interleaved row stride in bf16 elems (hi+lo)
#define WELEMS  ((size_t)HD * RSTRIDE)

#define BM 128
#define BN 128
#define NTH 256

// smem: 1024 B header (bias) + 3 stages x 32 KB (A 16K + W 16K)
#define A_OFF  0u
#define W_OFF  16384u
#define STAGE  32768u
#define NSTAGE 3
#define SMEMB  (1024u + NSTAGE*STAGE)   // 99328

// ------------- scratch (static device arrays, no runtime alloc) -------------
__device__ bf16  g_Xhl [(size_t)MROWS * RSTRIDE];
__device__ bf16  g_H0hl[(size_t)MROWS * RSTRIDE];
__device__ bf16  g_H1hl[(size_t)MROWS * RSTRIDE];
__device__ bf16  g_Whl [4 * WELEMS];
__device__ float g_beff[2 * HD];

// ----------------------------- PTX helpers ----------------------------------
__device__ __forceinline__ uint32_t s2u(const void* p) {
    uint32_t a;
    asm("{ .reg .u64 t; cvta.to.shared.u64 t, %1; cvt.u32.u64 %0, t; }" : "=r"(a) : "l"(p));
    return a;
}
__device__ __forceinline__ void cp16(uint32_t dst, const void* src) {
    asm volatile("cp.async.cg.shared.global [%0], [%1], 16;" :: "r"(dst), "l"(src));
}
#define CP_COMMIT() asm volatile("cp.async.commit_group;" ::: "memory")

__device__ __forceinline__ void ldsm4(uint32_t& r0, uint32_t& r1, uint32_t& r2,
                                      uint32_t& r3, uint32_t addr) {
    asm volatile("ldmatrix.sync.aligned.m8n8.x4.shared.b16 {%0,%1,%2,%3}, [%4];"
                 : "=r"(r0), "=r"(r1), "=r"(r2), "=r"(r3) : "r"(addr));
}
__device__ __forceinline__ void mma16816(float* c, const uint32_t* a, const uint32_t* b) {
    asm volatile(
        "mma.sync.aligned.m16n8k16.row.col.f32.bf16.bf16.f32 "
        "{%0,%1,%2,%3}, {%4,%5,%6,%7}, {%8,%9}, {%0,%1,%2,%3};"
        : "+f"(c[0]), "+f"(c[1]), "+f"(c[2]), "+f"(c[3])
        : "r"(a[0]), "r"(a[1]), "r"(a[2]), "r"(a[3]), "r"(b[0]), "r"(b[1]));
}

// fast accurate tanh: 1 - 2/(exp(2x)+1)
__device__ __forceinline__ float tfast(float x) {
    float e, r;
    asm("ex2.approx.f32 %0, %1;" : "=f"(e) : "f"(x * 2.8853900817779268f));
    asm("rcp.approx.f32 %0, %1;" : "=f"(r) : "f"(e + 1.0f));
    return fmaf(-2.0f, r, 1.0f);
}

__device__ __forceinline__ void split2(float x, bf16& h, bf16& l) {
    h = __float2bfloat16_rn(x);
    l = __float2bfloat16_rn(x - __bfloat162float(h));
}

// ---------------------------- GEMM stage kernel -----------------------------
// acc[m][n] = sum_k A[m][k]*W[n][k] + bias, opt tanh.
// Interleaved hi/lo layout: row = 16 chunks of [32 hi bf16 | 32 lo bf16].
// Computes Ah*Wh + Ah*Wl + Al*Wh with fp32 accumulation.
template<bool DO_TANH, bool HSF, bool TRANS>
__global__ void __launch_bounds__(NTH, 2) gemm_stage(
    const bf16* __restrict__ A0, const bf16* __restrict__ W0,
    const float* __restrict__ bias0, const float* __restrict__ bias1,
    bf16* __restrict__ outHL, float* __restrict__ outF, float* __restrict__ hsf)
{
    extern __shared__ char smem[];
    const uint32_t sb = s2u(smem);
    const int t   = threadIdx.x;
    const int wid = t >> 5;
    const int lid = t & 31;
    const int n0  = blockIdx.x * BN;
    const int m0  = blockIdx.y * BM;
    const int wm  = wid & 3;       // 0..3 (M, 32 rows)
    const int wn  = wid >> 2;      // 0..1 (N, 64 cols)

    if (t < BN) {
        float b = bias0[n0 + t];
        if (bias1) b += bias1[n0 + t];
        ((float*)smem)[t] = b;
    }

    float acc[2][8][4];
#pragma unroll
    for (int mt = 0; mt < 2; ++mt)
#pragma unroll
        for (int nt = 0; nt < 8; ++nt)
#pragma unroll
            for (int e = 0; e < 4; ++e) acc[mt][nt][e] = 0.0f;

    const int q   = lid >> 3;
    const int lr8 = lid & 7;
    const int sws = lr8;
    const uint32_t aOff = (uint32_t)((wm * 32 + (q & 1) * 8 + lr8) * 128);
    const int aHalf = q >> 1;
    const uint32_t bOff = (uint32_t)((wn * 64 + (q >> 1) * 8 + lr8) * 128);
    const int bHalf = q & 1;

    const int NC = 16;   // KC=32 chunks over K=512

    auto load_chunk = [&](int cc) {
        const int kc = cc;
        const uint32_t st = sb + 1024 + (uint32_t)(cc % NSTAGE) * STAGE;
#pragma unroll
        for (int i = 0; i < 4; ++i) {                 // A: 128 rows x 8 c16
            int idx = t + i * NTH;
            int r = idx >> 3, c = idx & 7;
            uint32_t d = st + A_OFF + r * 128 + (uint32_t)((c ^ (r & 7)) << 4);
            cp16(d, A0 + (size_t)(m0 + r) * RSTRIDE + kc * 64 + c * 8);
        }
#pragma unroll
        for (int i = 0; i < 4; ++i) {                 // W: 128 rows x 8 c16
            int idx = t + i * NTH;
            int r = idx >> 3, c = idx & 7;
            uint32_t d = st + W_OFF + r * 128 + (uint32_t)((c ^ (r & 7)) << 4);
            cp16(d, W0 + (size_t)(n0 + r) * RSTRIDE + kc * 64 + c * 8);
        }
        CP_COMMIT();
    };

    load_chunk(0);
    load_chunk(1);

#pragma unroll 1
    for (int cc = 0; cc < NC; ++cc) {
        if (cc < NC - 1) asm volatile("cp.async.wait_group 1;" ::: "memory");
        else             asm volatile("cp.async.wait_group 0;" ::: "memory");
        __syncthreads();
        if (cc + 2 < NC) load_chunk(cc + 2);

        const uint32_t st = sb + 1024 + (uint32_t)(cc % NSTAGE) * STAGE;
        const uint32_t aB = st + A_OFF + aOff;
        const uint32_t bB = st + W_OFF + bOff;

#pragma unroll
        for (int ks = 0; ks < 2; ++ks) {
            const uint32_t caH = (uint32_t)(((2 * ks + aHalf) ^ sws) << 4);
            const uint32_t caL = (uint32_t)(((4 + 2 * ks + aHalf) ^ sws) << 4);
            const uint32_t cbH = (uint32_t)(((2 * ks + bHalf) ^ sws) << 4);
            const uint32_t cbL = (uint32_t)(((4 + 2 * ks + bHalf) ^ sws) << 4);
            uint32_t a[2][4], b[8][2];

            // A_hi
#pragma unroll
            for (int mt = 0; mt < 2; ++mt)
                ldsm4(a[mt][0], a[mt][1], a[mt][2], a[mt][3],
                      aB + mt * 2048 + caH);
            // W_lo -> acc += Ah*Wl
#pragma unroll
            for (int bt = 0; bt < 4; ++bt)
                ldsm4(b[2*bt][0], b[2*bt][1], b[2*bt+1][0], b[2*bt+1][1],
                      bB + bt * 2048 + cbL);
#pragma unroll
            for (int mt = 0; mt < 2; ++mt)
#pragma unroll
                for (int nt = 0; nt < 8; ++nt)
                    mma16816(acc[mt][nt], a[mt], b[nt]);
            // W_hi -> acc += Ah*Wh
#pragma unroll
            for (int bt = 0; bt < 4; ++bt)
                ldsm4(b[2*bt][0], b[2*bt][1], b[2*bt+1][0], b[2*bt+1][1],
                      bB + bt * 2048 + cbH);
#pragma unroll
            for (int mt = 0; mt < 2; ++mt)
#pragma unroll
                for (int nt = 0; nt < 8; ++nt)
                    mma16816(acc[mt][nt], a[mt], b[nt]);
            // A_lo -> acc += Al*Wh
#pragma unroll
            for (int mt = 0; mt < 2; ++mt)
                ldsm4(a[mt][0], a[mt][1], a[mt][2], a[mt][3],
                      aB + mt * 2048 + caL);
#pragma unroll
            for (int mt = 0; mt < 2; ++mt)
#pragma unroll
                for (int nt = 0; nt < 8; ++nt)
                    mma16816(acc[mt][nt], a[mt], b[nt]);
        }
    }

    // ------------------------------ epilogue --------------------------------
    const float* bsm = (const float*)smem;
    const int lq = lid >> 2;
    const int lr = lid & 3;

#pragma unroll
    for (int mt = 0; mt < 2; ++mt) {
#pragma unroll
        for (int hf = 0; hf < 2; ++hf) {
            const int m = m0 + wm * 32 + mt * 16 + lq + hf * 8;
#pragma unroll
            for (int nt = 0; nt < 8; ++nt) {
                const int n = n0 + wn * 64 + nt * 8 + lr * 2;
                float x0 = acc[mt][nt][hf * 2 + 0] + bsm[n - n0];
                float x1 = acc[mt][nt][hf * 2 + 1] + bsm[n - n0 + 1];
                if (DO_TANH) { x0 = tfast(x0); x1 = tfast(x1); }

                if (TRANS) {
                    const int s = m & 4095, bb = m >> 12;
                    float* dst = outF + ((size_t)(s * 8 + bb)) * HD + n;
                    *(float2*)dst = make_float2(x0, x1);
                } else {
                    __nv_bfloat162 hh, ll;
                    split2(x0, hh.x, ll.x);
                    split2(x1, hh.y, ll.y);
                    bf16* base = outHL + (size_t)m * RSTRIDE + (n >> 5) * 64;
                    const int w = n & 31;
                    *(__nv_bfloat162*)(base + w)      = hh;
                    *(__nv_bfloat162*)(base + 32 + w) = ll;
                }
                if (HSF && ((m & 4095) == 4095)) {
                    float* hd = hsf + (size_t)(m >> 12) * HD + n;
                    *(float2*)hd = make_float2(x0, x1);
                }
            }
        }
    }
}

// --------------------------- fused prep kernel -------------------------------
// One launch doing all preprocessing; block ranges dispatch sub-tasks so the
// compute-heavy weff blocks overlap with the memory-heavy split_x blocks.
//   blocks [0,128)      : Weff = Whh + Wxh@Why -> interleaved bf16 (g_Whl 1,2)
//   blocks [128,256)    : beff = bhh + bxh + Wxh@bhy (warp reductions)
//   blocks [256,2304)   : split X -> g_Xhl
//   blocks [2304,2368)  : split W_xh0 / final projection -> g_Whl 0,3
struct PrepP {
    const float* Wxh[2];   // layer Wxh
    const float* Why[2];   // previous-cell Why
    const float* Whh[2];   // layer Whh
    bf16*        WeffC[2]; // interleaved dst
    const float* bhh[2];
    const float* bxh[2];
    const float* bhy[2];
    float*       beff[2];
    const float* xs;
    bf16*        Xhl;
    const float* Wraw[2];  // raw split: W_xh0, final proj
    bf16*        Whl;      // base of g_Whl
};

__device__ void prep_weff(const PrepP& p, int id, int t)
{
    const int l  = id >> 6;
    const int rm = id & 63;
    const int m0 = (rm >> 3) * 64;
    const int n0 = (rm & 7) * 64;
    const float* __restrict__ A = p.Wxh[l];
    const float* __restrict__ B = p.Why[l];
    const float* __restrict__ Wadd = p.Whh[l];
    bf16* __restrict__ C = p.WeffC[l];

    __shared__ float As[16][64];
    __shared__ float Bs[16][64];
    const int tx = t & 15, ty = t >> 4;

    float acc[4][4] = {};
#pragma unroll 1
    for (int kt = 0; kt < 512; kt += 16) {
#pragma unroll
        for (int e = t; e < 1024; e += 256) {
            int am = e >> 4, ak = e & 15;
            As[ak][am] = A[(size_t)(m0 + am) * 512 + kt + ak];
            int bj = e & 63, bk = e >> 6;
            Bs[bk][bj] = B[(size_t)(kt + bk) * 512 + n0 + bj];
        }
        __syncthreads();
#pragma unroll
        for (int k = 0; k < 16; ++k) {
            float af[4], bf[4];
#pragma unroll
            for (int i = 0; i < 4; ++i) af[i] = As[k][ty * 4 + i];
#pragma unroll
            for (int j = 0; j < 4; ++j) bf[j] = Bs[k][tx * 4 + j];
#pragma unroll
            for (int i = 0; i < 4; ++i)
#pragma unroll
                for (int j = 0; j < 4; ++j)
                    acc[i][j] = fmaf(af[i], bf[j], acc[i][j]);
        }
        __syncthreads();
    }

    const int kcol = n0 + tx * 4;
#pragma unroll
    for (int i = 0; i < 4; ++i) {
        const int n = m0 + ty * 4 + i;
        bf16 h[4], lo[4];
#pragma unroll
        for (int j = 0; j < 4; ++j) {
            float v = Wadd[(size_t)n * 512 + kcol + j] + acc[i][j];
            split2(v, h[j], lo[j]);
        }
        bf16* base = C + (size_t)n * RSTRIDE + (kcol >> 5) * 64 + (kcol & 31);
        *(uint2*)base        = *(uint2*)h;
        *(uint2*)(base + 32) = *(uint2*)lo;
    }
}

__device__ void prep_beff(const PrepP& p, int id, int t)
{
    const int gw = id * 8 + (t >> 5);    // 1024 warps
    const int l = gw >> 9;
    const int n = gw & 511;
    const int lane = t & 31;
    const float* W  = p.Wxh[l] + (size_t)n * 512 + lane * 16;
    const float* bh = p.bhy[l] + lane * 16;
    float s = 0.0f;
#pragma unroll
    for (int k = 0; k < 16; k += 4) {
        float4 w = *(const float4*)(W + k);
        float4 b = *(const float4*)(bh + k);
        s = fmaf(w.x, b.x, s); s = fmaf(w.y, b.y, s);
        s = fmaf(w.z, b.z, s); s = fmaf(w.w, b.w, s);
    }
#pragma unroll
    for (int o = 16; o; o >>= 1) s += __shfl_xor_sync(0xFFFFFFFFu, s, o);
    if (lane == 0) p.beff[l][n] = p.bhh[l][n] + p.bxh[l][n] + s;
}

__device__ void prep_split(const float* __restrict__ src0, bf16* __restrict__ d)
{
    uint32_t hi[16], lo[16];
#pragma unroll
    for (int j = 0; j < 8; ++j) {
        float4 v = *(const float4*)(src0 + j * 4);
        __nv_bfloat162 h0, l0, h1, l1;
        split2(v.x, h0.x, l0.x); split2(v.y, h0.y, l0.y);
        split2(v.z, h1.x, l1.x); split2(v.w, h1.y, l1.y);
        hi[2*j]   = *(uint32_t*)&h0; hi[2*j+1] = *(uint32_t*)&h1;
        lo[2*j]   = *(uint32_t*)&l0; lo[2*j+1] = *(uint32_t*)&l1;
    }
#pragma unroll
    for (int j = 0; j < 4; ++j) {
        ((uint4*)d)[j]      = *(uint4*)(hi + 4*j);
        ((uint4*)(d+32))[j] = *(uint4*)(lo + 4*j);
    }
}

__global__ void __launch_bounds__(256) k_prep(PrepP p)
{
    const int bid = blockIdx.x;
    const int t   = threadIdx.x;

    if (bid < 128) {
        prep_weff(p, bid, t);
    } else if (bid < 256) {
        prep_beff(p, bid - 128, t);
    } else if (bid < 2304) {
        const size_t idx = (size_t)(bid - 256) * 256 + t;
        const size_t row = idx >> 4;
        const int    kc  = (int)(idx & 15);
        prep_split(p.xs + row * 512 + kc * 32,
                   p.Xhl + row * RSTRIDE + kc * 64);
    } else {
        const size_t idx = (size_t)(bid - 2304) * 256 + t;
        const int slot = (int)(idx >> 13);           // 0 or 1
        const size_t row = (idx >> 4) & 511;
        const int    kc  = (int)(idx & 15);
        // slot 0 -> Whl slot 0 (W_xh0), slot 1 -> Whl slot 3 (final projection)
        prep_split(p.Wraw[slot] + row * 512 + kc * 32,
                   p.Whl + (size_t)(slot * 3) * WELEMS + row * RSTRIDE + kc * 64);
    }
}

// --------------------------------- launcher ---------------------------------
extern "C" void kernel_launch(void* const* d_in, const int* in_sizes, int n_in,
                              void* d_out, int out_size)
{
    const float* xs     = (const float*)d_in[0];
    const float* W_xh0  = (const float*)d_in[1];
    const float* b_xh0  = (const float*)d_in[2];
    const float* b_hh0  = (const float*)d_in[4];
    const float* W_hy0  = (const float*)d_in[5];
    const float* b_hy0  = (const float*)d_in[6];
    const float* W_xh_h = (const float*)d_in[7];
    const float* b_xh_h = (const float*)d_in[8];
    const float* W_hh_h = (const float*)d_in[9];
    const float* b_hh_h = (const float*)d_in[10];
    const float* W_hy_h = (const float*)d_in[11];
    const float* b_hy_h = (const float*)d_in[12];

    float* out = (float*)d_out;
    float* hs_final = out + (size_t)4096 * 8 * HD;

    bf16 *Xhl, *H0hl, *H1hl, *Whl;
    float *beff;
    cudaGetSymbolAddress((void**)&Xhl,  g_Xhl);
    cudaGetSymbolAddress((void**)&H0hl, g_H0hl);
    cudaGetSymbolAddress((void**)&H1hl, g_H1hl);
    cudaGetSymbolAddress((void**)&Whl,  g_Whl);
    cudaGetSymbolAddress((void**)&beff, g_beff);

    cudaFuncSetAttribute(gemm_stage<true,  false, false>,
                         cudaFuncAttributeMaxDynamicSharedMemorySize, SMEMB);
    cudaFuncSetAttribute(gemm_stage<true,  true,  false>,
                         cudaFuncAttributeMaxDynamicSharedMemorySize, SMEMB);
    cudaFuncSetAttribute(gemm_stage<false, false, true >,
                         cudaFuncAttributeMaxDynamicSharedMemorySize, SMEMB);

#define WS(s) (Whl + (size_t)(s) * WELEMS)

    // ---- fused prep (single launch: weff + beff + splits overlap) ----
    PrepP pp;
    pp.Wxh[0] = W_xh_h;      pp.Wxh[1] = W_xh_h + WSZ;
    pp.Why[0] = W_hy0;       pp.Why[1] = W_hy_h;
    pp.Whh[0] = W_hh_h;      pp.Whh[1] = W_hh_h + WSZ;
    pp.WeffC[0] = WS(1);     pp.WeffC[1] = WS(2);
    pp.bhh[0] = b_hh_h;      pp.bhh[1] = b_hh_h + HD;
    pp.bxh[0] = b_xh_h;      pp.bxh[1] = b_xh_h + HD;
    pp.bhy[0] = b_hy0;       pp.bhy[1] = b_hy_h;
    pp.beff[0] = beff;       pp.beff[1] = beff + HD;
    pp.xs  = xs;
    pp.Xhl = Xhl;
    pp.Wraw[0] = W_xh0;
    pp.Wraw[1] = W_hy_h + WSZ;
    pp.Whl = Whl;
    k_prep<<<2368, 256>>>(pp);

    dim3 grid(HD / BN, MROWS / BM);   // (4, 256) = 1024 CTAs
    dim3 block(NTH);

    // 1) h0 = tanh(X @ W_xh0^T + b_xh0 + b_hh0)
    gemm_stage<true, false, false><<<grid, block, SMEMB>>>(
        Xhl, WS(0), b_xh0, b_hh0, H0hl, nullptr, nullptr);
    // 2) h1 = tanh(h0 @ Weff0^T + beff0)
    gemm_stage<true, false, false><<<grid, block, SMEMB>>>(
        H0hl, WS(1), beff, nullptr, H1hl, nullptr, nullptr);
    // 3) h2 = tanh(h1 @ Weff1^T + beff1)  (+ hs_final)
    gemm_stage<true, true, false><<<grid, block, SMEMB>>>(
        H1hl, WS(2), beff + HD, nullptr, H0hl, nullptr, hs_final);
    // 4) outputs = (h2 @ W_hy_h[1]^T + b_hy_h[1]) -> [S, B, H] fp32
    gemm_stage<false, false, true><<<grid, block, SMEMB>>>(
        H0hl, WS(3), b_hy_h + HD, nullptr, nullptr, out, nullptr);
#undef WS
}

// round 11
// speedup vs baseline: 1.4451x; 1.1987x over previous
#include <cuda_runtime.h>
#include <cuda_fp16.h>
#include <math.h>
#include <cstdint>
#include <cstddef>

typedef __half fp16;

#define MROWS 32768
#define HD    512
#define WSZ   (512*512)
#define RSTRIDE 1024            // activation row stride in fp16 elems (hi+lo interleaved)
#define WELEMS  ((size_t)WSZ)   // weights: single fp16 plane

#define BM 128
#define BN 128
#define NTH 256

// smem: 1024 B header (bias) + 4 stages x 24 KB (A 16K hi/lo + W 8K single plane)
#define A_OFF  0u
#define W_OFF  16384u
#define STAGE  24576u
#define NSTAGE 4
#define SMEMB  (1024u + NSTAGE*STAGE)   // 99328

// ------------- scratch (static device arrays, no runtime alloc) -------------
__device__ fp16  g_Xhl [(size_t)MROWS * RSTRIDE];
__device__ fp16  g_H0hl[(size_t)MROWS * RSTRIDE];
__device__ fp16  g_H1hl[(size_t)MROWS * RSTRIDE];
__device__ fp16  g_W   [4 * WELEMS];
__device__ float g_beff[2 * HD];

// ----------------------------- PTX helpers ----------------------------------
__device__ __forceinline__ uint32_t s2u(const void* p) {
    uint32_t a;
    asm("{ .reg .u64 t; cvta.to.shared.u64 t, %1; cvt.u32.u64 %0, t; }" : "=r"(a) : "l"(p));
    return a;
}
__device__ __forceinline__ void cp16(uint32_t dst, const void* src) {
    asm volatile("cp.async.cg.shared.global [%0], [%1], 16;" :: "r"(dst), "l"(src));
}
#define CP_COMMIT() asm volatile("cp.async.commit_group;" ::: "memory")

__device__ __forceinline__ void ldsm4(uint32_t& r0, uint32_t& r1, uint32_t& r2,
                                      uint32_t& r3, uint32_t addr) {
    asm volatile("ldmatrix.sync.aligned.m8n8.x4.shared.b16 {%0,%1,%2,%3}, [%4];"
                 : "=r"(r0), "=r"(r1), "=r"(r2), "=r"(r3) : "r"(addr));
}
__device__ __forceinline__ void mma16816(float* c, const uint32_t* a, const uint32_t* b) {
    asm volatile(
        "mma.sync.aligned.m16n8k16.row.col.f32.f16.f16.f32 "
        "{%0,%1,%2,%3}, {%4,%5,%6,%7}, {%8,%9}, {%0,%1,%2,%3};"
        : "+f"(c[0]), "+f"(c[1]), "+f"(c[2]), "+f"(c[3])
        : "r"(a[0]), "r"(a[1]), "r"(a[2]), "r"(a[3]), "r"(b[0]), "r"(b[1]));
}

// fast accurate tanh: 1 - 2/(exp(2x)+1)
__device__ __forceinline__ float tfast(float x) {
    float e, r;
    asm("ex2.approx.f32 %0, %1;" : "=f"(e) : "f"(x * 2.8853900817779268f));
    asm("rcp.approx.f32 %0, %1;" : "=f"(r) : "f"(e + 1.0f));
    return fmaf(-2.0f, r, 1.0f);
}

__device__ __forceinline__ void split2(float x, fp16& h, fp16& l) {
    h = __float2half_rn(x);
    l = __float2half_rn(x - __half2float(h));
}

// ---------------------------- GEMM stage kernel -----------------------------
// acc[m][n] = sum_k A[m][k]*W[n][k] + bias, opt tanh.
// A: fp16 hi/lo interleaved rows (16 chunks of [32 hi | 32 lo]) — 22-bit.
// W: single fp16 plane [n][k], row stride 512.
// Computes (Ah + Al) * W  with fp32 accumulation: 2 MMA combos per fragment.
template<bool DO_TANH, bool HSF, bool TRANS>
__global__ void __launch_bounds__(NTH, 2) gemm_stage(
    const fp16* __restrict__ A0, const fp16* __restrict__ W0,
    const float* __restrict__ bias0, const float* __restrict__ bias1,
    fp16* __restrict__ outHL, float* __restrict__ outF, float* __restrict__ hsf)
{
    extern __shared__ char smem[];
    const uint32_t sb = s2u(smem);
    const int t   = threadIdx.x;
    const int wid = t >> 5;
    const int lid = t & 31;
    const int n0  = blockIdx.x * BN;
    const int m0  = blockIdx.y * BM;
    const int wm  = wid & 3;       // 0..3 (M, 32 rows)
    const int wn  = wid >> 2;      // 0..1 (N, 64 cols)

    if (t < BN) {
        float b = bias0[n0 + t];
        if (bias1) b += bias1[n0 + t];
        ((float*)smem)[t] = b;
    }

    float acc[2][8][4];
#pragma unroll
    for (int mt = 0; mt < 2; ++mt)
#pragma unroll
        for (int nt = 0; nt < 8; ++nt)
#pragma unroll
            for (int e = 0; e < 4; ++e) acc[mt][nt][e] = 0.0f;

    // ldmatrix per-lane addressing
    const int q   = lid >> 3;        // quadrant 0..3
    const int lr8 = lid & 7;
    const int swsA = lr8;            // A swizzle key (128 B rows, 8 cols)
    const int swsB = lr8 & 3;        // W swizzle key (64 B rows, 4 cols)
    const uint32_t aOff = (uint32_t)((wm * 32 + (q & 1) * 8 + lr8) * 128);
    const int aHalf = q >> 1;
    const uint32_t bOff = (uint32_t)((wn * 64 + (q >> 1) * 8 + lr8) * 64);
    const int bHalf = q & 1;

    const int NC = 16;   // KC=32 chunks over K=512

    auto load_chunk = [&](int cc) {
        const int kc = cc;
        const uint32_t st = sb + 1024 + (uint32_t)(cc % NSTAGE) * STAGE;
#pragma unroll
        for (int i = 0; i < 4; ++i) {                 // A: 128 rows x 8 c16 (hi|lo)
            int idx = t + i * NTH;
            int r = idx >> 3, c = idx & 7;
            uint32_t d = st + A_OFF + r * 128 + (uint32_t)((c ^ (r & 7)) << 4);
            cp16(d, A0 + (size_t)(m0 + r) * RSTRIDE + kc * 64 + c * 8);
        }
#pragma unroll
        for (int i = 0; i < 2; ++i) {                 // W: 128 rows x 4 c16
            int idx = t + i * NTH;
            int r = idx >> 2, c = idx & 3;
            uint32_t d = st + W_OFF + r * 64 + (uint32_t)((c ^ (r & 3)) << 4);
            cp16(d, W0 + (size_t)(n0 + r) * 512 + kc * 32 + c * 8);
        }
        CP_COMMIT();
    };

    load_chunk(0);
    load_chunk(1);
    load_chunk(2);

#pragma unroll 1
    for (int cc = 0; cc < NC; ++cc) {
        if (cc < NC - 2)      asm volatile("cp.async.wait_group 2;" ::: "memory");
        else if (cc == NC - 2) asm volatile("cp.async.wait_group 1;" ::: "memory");
        else                  asm volatile("cp.async.wait_group 0;" ::: "memory");
        __syncthreads();
        if (cc + 3 < NC) load_chunk(cc + 3);

        const uint32_t st = sb + 1024 + (uint32_t)(cc % NSTAGE) * STAGE;
        const uint32_t aB = st + A_OFF + aOff;
        const uint32_t bB = st + W_OFF + bOff;

#pragma unroll
        for (int ks = 0; ks < 2; ++ks) {
            // A chunk columns: hi = 0..3, lo = 4..7 (128 B rows)
            const uint32_t caH = (uint32_t)(((2 * ks + aHalf) ^ swsA) << 4);
            const uint32_t caL = (uint32_t)(((4 + 2 * ks + aHalf) ^ swsA) << 4);
            // W chunk columns: 0..3 (64 B rows)
            const uint32_t cb  = (uint32_t)(((2 * ks + bHalf) ^ swsB) << 4);
            uint32_t a[2][4], b[8][2];

            // W fragments (single plane)
#pragma unroll
            for (int bt = 0; bt < 4; ++bt)
                ldsm4(b[2*bt][0], b[2*bt][1], b[2*bt+1][0], b[2*bt+1][1],
                      bB + bt * 1024 + cb);
            // A_hi -> acc += Ah*W
#pragma unroll
            for (int mt = 0; mt < 2; ++mt)
                ldsm4(a[mt][0], a[mt][1], a[mt][2], a[mt][3],
                      aB + mt * 2048 + caH);
#pragma unroll
            for (int mt = 0; mt < 2; ++mt)
#pragma unroll
                for (int nt = 0; nt < 8; ++nt)
                    mma16816(acc[mt][nt], a[mt], b[nt]);
            // A_lo -> acc += Al*W
#pragma unroll
            for (int mt = 0; mt < 2; ++mt)
                ldsm4(a[mt][0], a[mt][1], a[mt][2], a[mt][3],
                      aB + mt * 2048 + caL);
#pragma unroll
            for (int mt = 0; mt < 2; ++mt)
#pragma unroll
                for (int nt = 0; nt < 8; ++nt)
                    mma16816(acc[mt][nt], a[mt], b[nt]);
        }
    }

    // ------------------------------ epilogue --------------------------------
    const float* bsm = (const float*)smem;
    const int lq = lid >> 2;
    const int lr = lid & 3;

#pragma unroll
    for (int mt = 0; mt < 2; ++mt) {
#pragma unroll
        for (int hf = 0; hf < 2; ++hf) {
            const int m = m0 + wm * 32 + mt * 16 + lq + hf * 8;
#pragma unroll
            for (int nt = 0; nt < 8; ++nt) {
                const int n = n0 + wn * 64 + nt * 8 + lr * 2;
                float x0 = acc[mt][nt][hf * 2 + 0] + bsm[n - n0];
                float x1 = acc[mt][nt][hf * 2 + 1] + bsm[n - n0 + 1];
                if (DO_TANH) { x0 = tfast(x0); x1 = tfast(x1); }

                if (TRANS) {
                    const int s = m & 4095, bb = m >> 12;
                    float* dst = outF + ((size_t)(s * 8 + bb)) * HD + n;
                    *(float2*)dst = make_float2(x0, x1);
                } else {
                    __half2 hh, ll;
                    split2(x0, hh.x, ll.x);
                    split2(x1, hh.y, ll.y);
                    fp16* base = outHL + (size_t)m * RSTRIDE + (n >> 5) * 64;
                    const int w = n & 31;
                    *(__half2*)(base + w)      = hh;
                    *(__half2*)(base + 32 + w) = ll;
                }
                if (HSF && ((m & 4095) == 4095)) {
                    float* hd = hsf + (size_t)(m >> 12) * HD + n;
                    *(float2*)hd = make_float2(x0, x1);
                }
            }
        }
    }
}

// --------------------------- fused prep kernel -------------------------------
//   blocks [0,128)      : Weff = Whh + Wxh@Why -> fp16 single plane (slots 1,2)
//   blocks [128,256)    : beff = bhh + bxh + Wxh@bhy (warp reductions)
//   blocks [256,2304)   : split X -> g_Xhl (fp16 hi/lo)
//   blocks [2304,2368)  : convert W_xh0 / final projection -> fp16 (slots 0,3)
struct PrepP {
    const float* Wxh[2];
    const float* Why[2];
    const float* Whh[2];
    fp16*        WeffC[2];
    const float* bhh[2];
    const float* bxh[2];
    const float* bhy[2];
    float*       beff[2];
    const float* xs;
    fp16*        Xhl;
    const float* Wraw[2];
    fp16*        Wbase;
};

__device__ void prep_weff(const PrepP& p, int id, int t)
{
    const int l  = id >> 6;
    const int rm = id & 63;
    const int m0 = (rm >> 3) * 64;
    const int n0 = (rm & 7) * 64;
    const float* __restrict__ A = p.Wxh[l];
    const float* __restrict__ B = p.Why[l];
    const float* __restrict__ Wadd = p.Whh[l];
    fp16* __restrict__ C = p.WeffC[l];

    __shared__ float As[16][64];
    __shared__ float Bs[16][64];
    const int tx = t & 15, ty = t >> 4;

    float acc[4][4] = {};
#pragma unroll 1
    for (int kt = 0; kt < 512; kt += 16) {
#pragma unroll
        for (int e = t; e < 1024; e += 256) {
            int am = e >> 4, ak = e & 15;
            As[ak][am] = A[(size_t)(m0 + am) * 512 + kt + ak];
            int bj = e & 63, bk = e >> 6;
            Bs[bk][bj] = B[(size_t)(kt + bk) * 512 + n0 + bj];
        }
        __syncthreads();
#pragma unroll
        for (int k = 0; k < 16; ++k) {
            float af[4], bf[4];
#pragma unroll
            for (int i = 0; i < 4; ++i) af[i] = As[k][ty * 4 + i];
#pragma unroll
            for (int j = 0; j < 4; ++j) bf[j] = Bs[k][tx * 4 + j];
#pragma unroll
            for (int i = 0; i < 4; ++i)
#pragma unroll
                for (int j = 0; j < 4; ++j)
                    acc[i][j] = fmaf(af[i], bf[j], acc[i][j]);
        }
        __syncthreads();
    }

    const int kcol = n0 + tx * 4;
#pragma unroll
    for (int i = 0; i < 4; ++i) {
        const int n = m0 + ty * 4 + i;
        fp16 h4[4];
#pragma unroll
        for (int j = 0; j < 4; ++j)
            h4[j] = __float2half_rn(Wadd[(size_t)n * 512 + kcol + j] + acc[i][j]);
        *(uint2*)(C + (size_t)n * 512 + kcol) = *(uint2*)h4;
    }
}

__device__ void prep_beff(const PrepP& p, int id, int t)
{
    const int gw = id * 8 + (t >> 5);
    const int l = gw >> 9;
    const int n = gw & 511;
    const int lane = t & 31;
    const float* W  = p.Wxh[l] + (size_t)n * 512 + lane * 16;
    const float* bh = p.bhy[l] + lane * 16;
    float s = 0.0f;
#pragma unroll
    for (int k = 0; k < 16; k += 4) {
        float4 w = *(const float4*)(W + k);
        float4 b = *(const float4*)(bh + k);
        s = fmaf(w.x, b.x, s); s = fmaf(w.y, b.y, s);
        s = fmaf(w.z, b.z, s); s = fmaf(w.w, b.w, s);
    }
#pragma unroll
    for (int o = 16; o; o >>= 1) s += __shfl_xor_sync(0xFFFFFFFFu, s, o);
    if (lane == 0) p.beff[l][n] = p.bhh[l][n] + p.bxh[l][n] + s;
}

__device__ void prep_split_x(const float* __restrict__ src0, fp16* __restrict__ d)
{
    uint32_t hi[16], lo[16];
#pragma unroll
    for (int j = 0; j < 8; ++j) {
        float4 v = *(const float4*)(src0 + j * 4);
        __half2 h0, l0, h1, l1;
        split2(v.x, h0.x, l0.x); split2(v.y, h0.y, l0.y);
        split2(v.z, h1.x, l1.x); split2(v.w, h1.y, l1.y);
        hi[2*j]   = *(uint32_t*)&h0; hi[2*j+1] = *(uint32_t*)&h1;
        lo[2*j]   = *(uint32_t*)&l0; lo[2*j+1] = *(uint32_t*)&l1;
    }
#pragma unroll
    for (int j = 0; j < 4; ++j) {
        ((uint4*)d)[j]      = *(uint4*)(hi + 4*j);
        ((uint4*)(d+32))[j] = *(uint4*)(lo + 4*j);
    }
}

__device__ void prep_cvt_w(const float* __restrict__ src0, fp16* __restrict__ d)
{
    uint32_t h[16];
#pragma unroll
    for (int j = 0; j < 8; ++j) {
        float4 v = *(const float4*)(src0 + j * 4);
        __half2 h0, h1;
        h0.x = __float2half_rn(v.x); h0.y = __float2half_rn(v.y);
        h1.x = __float2half_rn(v.z); h1.y = __float2half_rn(v.w);
        h[2*j] = *(uint32_t*)&h0; h[2*j+1] = *(uint32_t*)&h1;
    }
#pragma unroll
    for (int j = 0; j < 4; ++j)
        ((uint4*)d)[j] = *(uint4*)(h + 4*j);
}

__global__ void __launch_bounds__(256) k_prep(PrepP p)
{
    const int bid = blockIdx.x;
    const int t   = threadIdx.x;

    if (bid < 128) {
        prep_weff(p, bid, t);
    } else if (bid < 256) {
        prep_beff(p, bid - 128, t);
    } else if (bid < 2304) {
        const size_t idx = (size_t)(bid - 256) * 256 + t;
        const size_t row = idx >> 4;
        const int    kc  = (int)(idx & 15);
        prep_split_x(p.xs + row * 512 + kc * 32,
                     p.Xhl + row * RSTRIDE + kc * 64);
    } else {
        const size_t idx = (size_t)(bid - 2304) * 256 + t;
        const int slot = (int)(idx >> 13);           // 0 or 1
        const size_t row = (idx >> 4) & 511;
        const int    kc  = (int)(idx & 15);
        // slot 0 -> W slot 0 (W_xh0), slot 1 -> W slot 3 (final projection)
        prep_cvt_w(p.Wraw[slot] + row * 512 + kc * 32,
                   p.Wbase + (size_t)(slot * 3) * WELEMS + row * 512 + kc * 32);
    }
}

// --------------------------------- launcher ---------------------------------
extern "C" void kernel_launch(void* const* d_in, const int* in_sizes, int n_in,
                              void* d_out, int out_size)
{
    const float* xs     = (const float*)d_in[0];
    const float* W_xh0  = (const float*)d_in[1];
    const float* b_xh0  = (const float*)d_in[2];
    const float* b_hh0  = (const float*)d_in[4];
    const float* W_hy0  = (const float*)d_in[5];
    const float* b_hy0  = (const float*)d_in[6];
    const float* W_xh_h = (const float*)d_in[7];
    const float* b_xh_h = (const float*)d_in[8];
    const float* W_hh_h = (const float*)d_in[9];
    const float* b_hh_h = (const float*)d_in[10];
    const float* W_hy_h = (const float*)d_in[11];
    const float* b_hy_h = (const float*)d_in[12];

    float* out = (float*)d_out;
    float* hs_final = out + (size_t)4096 * 8 * HD;

    fp16 *Xhl, *H0hl, *H1hl, *Wb;
    float *beff;
    cudaGetSymbolAddress((void**)&Xhl,  g_Xhl);
    cudaGetSymbolAddress((void**)&H0hl, g_H0hl);
    cudaGetSymbolAddress((void**)&H1hl, g_H1hl);
    cudaGetSymbolAddress((void**)&Wb,   g_W);
    cudaGetSymbolAddress((void**)&beff, g_beff);

    cudaFuncSetAttribute(gemm_stage<true,  false, false>,
                         cudaFuncAttributeMaxDynamicSharedMemorySize, SMEMB);
    cudaFuncSetAttribute(gemm_stage<true,  true,  false>,
                         cudaFuncAttributeMaxDynamicSharedMemorySize, SMEMB);
    cudaFuncSetAttribute(gemm_stage<false, false, true >,
                         cudaFuncAttributeMaxDynamicSharedMemorySize, SMEMB);

#define WS(s) (Wb + (size_t)(s) * WELEMS)

    // ---- fused prep ----
    PrepP pp;
    pp.Wxh[0] = W_xh_h;      pp.Wxh[1] = W_xh_h + WSZ;
    pp.Why[0] = W_hy0;       pp.Why[1] = W_hy_h;
    pp.Whh[0] = W_hh_h;      pp.Whh[1] = W_hh_h + WSZ;
    pp.WeffC[0] = WS(1);     pp.WeffC[1] = WS(2);
    pp.bhh[0] = b_hh_h;      pp.bhh[1] = b_hh_h + HD;
    pp.bxh[0] = b_xh_h;      pp.bxh[1] = b_xh_h + HD;
    pp.bhy[0] = b_hy0;       pp.bhy[1] = b_hy_h;
    pp.beff[0] = beff;       pp.beff[1] = beff + HD;
    pp.xs  = xs;
    pp.Xhl = Xhl;
    pp.Wraw[0] = W_xh0;
    pp.Wraw[1] = W_hy_h + WSZ;
    pp.Wbase = Wb;
    k_prep<<<2368, 256>>>(pp);

    dim3 grid(HD / BN, MROWS / BM);   // (4, 256) = 1024 CTAs
    dim3 block(NTH);

    // 1) h0 = tanh(X @ W_xh0^T + b_xh0 + b_hh0)
    gemm_stage<true, false, false><<<grid, block, SMEMB>>>(
        Xhl, WS(0), b_xh0, b_hh0, H0hl, nullptr, nullptr);
    // 2) h1 = tanh(h0 @ Weff0^T + beff0)
    gemm_stage<true, false, false><<<grid, block, SMEMB>>>(
        H0hl, WS(1), beff, nullptr, H1hl, nullptr, nullptr);
    // 3) h2 = tanh(h1 @ Weff1^T + beff1)  (+ hs_final)
    gemm_stage<true, true, false><<<grid, block, SMEMB>>>(
        H1hl, WS(2), beff + HD, nullptr, H0hl, nullptr, hs_final);
    // 4) outputs = (h2 @ W_hy_h[1]^T + b_hy_h[1]) -> [S, B, H] fp32
    gemm_stage<false, false, true><<<grid, block, SMEMB>>>(
        H0hl, WS(3), b_hy_h + HD, nullptr, nullptr, out, nullptr);
#undef WS
}

// round 12
// speedup vs baseline: 1.9165x; 1.3262x over previous
#include <cuda_runtime.h>
#include <cuda_fp16.h>
#include <math.h>
#include <cstdint>
#include <cstddef>

typedef __half fp16;

#define MROWS 32768
#define HD    512
#define WSZ   (512*512)
#define WELEMS  ((size_t)WSZ)

#define BM 128
#define BN 128
#define NTH 256

// smem: 1024 B header (bias) + 4 stages x 16 KB (A 8K + W 8K, single fp16 planes)
#define A_OFF  0u
#define W_OFF  8192u
#define STAGE  16384u
#define NSTAGE 4
#define SMEMB  (1024u + NSTAGE*STAGE)   // 66560

// ------------- scratch (static device arrays, no runtime alloc) -------------
__device__ fp16  g_X [(size_t)MROWS * HD];
__device__ fp16  g_H0[(size_t)MROWS * HD];
__device__ fp16  g_H1[(size_t)MROWS * HD];
__device__ fp16  g_W [4 * WELEMS];
__device__ float g_beff[2 * HD];

// ----------------------------- PTX helpers ----------------------------------
__device__ __forceinline__ uint32_t s2u(const void* p) {
    uint32_t a;
    asm("{ .reg .u64 t; cvta.to.shared.u64 t, %1; cvt.u32.u64 %0, t; }" : "=r"(a) : "l"(p));
    return a;
}
__device__ __forceinline__ void cp16(uint32_t dst, const void* src) {
    asm volatile("cp.async.cg.shared.global [%0], [%1], 16;" :: "r"(dst), "l"(src));
}
#define CP_COMMIT() asm volatile("cp.async.commit_group;" ::: "memory")

__device__ __forceinline__ void ldsm4(uint32_t& r0, uint32_t& r1, uint32_t& r2,
                                      uint32_t& r3, uint32_t addr) {
    asm volatile("ldmatrix.sync.aligned.m8n8.x4.shared.b16 {%0,%1,%2,%3}, [%4];"
                 : "=r"(r0), "=r"(r1), "=r"(r2), "=r"(r3) : "r"(addr));
}
__device__ __forceinline__ void mma16816(float* c, const uint32_t* a, const uint32_t* b) {
    asm volatile(
        "mma.sync.aligned.m16n8k16.row.col.f32.f16.f16.f32 "
        "{%0,%1,%2,%3}, {%4,%5,%6,%7}, {%8,%9}, {%0,%1,%2,%3};"
        : "+f"(c[0]), "+f"(c[1]), "+f"(c[2]), "+f"(c[3])
        : "r"(a[0]), "r"(a[1]), "r"(a[2]), "r"(a[3]), "r"(b[0]), "r"(b[1]));
}

// fast accurate tanh: 1 - 2/(exp(2x)+1)
__device__ __forceinline__ float tfast(float x) {
    float e, r;
    asm("ex2.approx.f32 %0, %1;" : "=f"(e) : "f"(x * 2.8853900817779268f));
    asm("rcp.approx.f32 %0, %1;" : "=f"(r) : "f"(e + 1.0f));
    return fmaf(-2.0f, r, 1.0f);
}

// ---------------------------- GEMM stage kernel -----------------------------
// acc[m][n] = sum_k A[m][k]*W[n][k] + bias, opt tanh.
// A, W: single fp16 planes, row stride 512. fp32 accumulation.
template<bool DO_TANH, bool HSF, bool TRANS>
__global__ void __launch_bounds__(NTH, 2) gemm_stage(
    const fp16* __restrict__ A0, const fp16* __restrict__ W0,
    const float* __restrict__ bias0, const float* __restrict__ bias1,
    fp16* __restrict__ outA, float* __restrict__ outF, float* __restrict__ hsf)
{
    extern __shared__ char smem[];
    const uint32_t sb = s2u(smem);
    const int t   = threadIdx.x;
    const int wid = t >> 5;
    const int lid = t & 31;
    const int n0  = blockIdx.x * BN;
    const int m0  = blockIdx.y * BM;
    const int wm  = wid & 3;       // 0..3 (M, 32 rows)
    const int wn  = wid >> 2;      // 0..1 (N, 64 cols)

    if (t < BN) {
        float b = bias0[n0 + t];
        if (bias1) b += bias1[n0 + t];
        ((float*)smem)[t] = b;
    }

    float acc[2][8][4];
#pragma unroll
    for (int mt = 0; mt < 2; ++mt)
#pragma unroll
        for (int nt = 0; nt < 8; ++nt)
#pragma unroll
            for (int e = 0; e < 4; ++e) acc[mt][nt][e] = 0.0f;

    // ldmatrix per-lane addressing (64 B rows: 4 chunk16 columns, swizzle key r&3)
    const int q   = lid >> 3;        // quadrant 0..3
    const int lr8 = lid & 7;
    const int sws = lr8 & 3;
    const uint32_t aOff = (uint32_t)((wm * 32 + (q & 1) * 8 + lr8) * 64);
    const int aHalf = q >> 1;
    const uint32_t bOff = (uint32_t)((wn * 64 + (q >> 1) * 8 + lr8) * 64);
    const int bHalf = q & 1;

    const int NC = 16;   // KC=32 chunks over K=512

    auto load_chunk = [&](int cc) {
        const int kc = cc;
        const uint32_t st = sb + 1024 + (uint32_t)(cc % NSTAGE) * STAGE;
#pragma unroll
        for (int i = 0; i < 2; ++i) {                 // A: 128 rows x 4 c16
            int idx = t + i * NTH;
            int r = idx >> 2, c = idx & 3;
            uint32_t d = st + A_OFF + r * 64 + (uint32_t)((c ^ (r & 3)) << 4);
            cp16(d, A0 + (size_t)(m0 + r) * HD + kc * 32 + c * 8);
        }
#pragma unroll
        for (int i = 0; i < 2; ++i) {                 // W: 128 rows x 4 c16
            int idx = t + i * NTH;
            int r = idx >> 2, c = idx & 3;
            uint32_t d = st + W_OFF + r * 64 + (uint32_t)((c ^ (r & 3)) << 4);
            cp16(d, W0 + (size_t)(n0 + r) * HD + kc * 32 + c * 8);
        }
        CP_COMMIT();
    };

    load_chunk(0);
    load_chunk(1);
    load_chunk(2);

#pragma unroll 1
    for (int cc = 0; cc < NC; ++cc) {
        if (cc < NC - 2)       asm volatile("cp.async.wait_group 2;" ::: "memory");
        else if (cc == NC - 2) asm volatile("cp.async.wait_group 1;" ::: "memory");
        else                   asm volatile("cp.async.wait_group 0;" ::: "memory");
        __syncthreads();
        if (cc + 3 < NC) load_chunk(cc + 3);

        const uint32_t st = sb + 1024 + (uint32_t)(cc % NSTAGE) * STAGE;
        const uint32_t aB = st + A_OFF + aOff;
        const uint32_t bB = st + W_OFF + bOff;

#pragma unroll
        for (int ks = 0; ks < 2; ++ks) {
            const uint32_t ca = (uint32_t)(((2 * ks + aHalf) ^ sws) << 4);
            const uint32_t cb = (uint32_t)(((2 * ks + bHalf) ^ sws) << 4);
            uint32_t a[2][4], b[8][2];

#pragma unroll
            for (int bt = 0; bt < 4; ++bt)
                ldsm4(b[2*bt][0], b[2*bt][1], b[2*bt+1][0], b[2*bt+1][1],
                      bB + bt * 1024 + cb);
#pragma unroll
            for (int mt = 0; mt < 2; ++mt)
                ldsm4(a[mt][0], a[mt][1], a[mt][2], a[mt][3],
                      aB + mt * 1024 + ca);
#pragma unroll
            for (int mt = 0; mt < 2; ++mt)
#pragma unroll
                for (int nt = 0; nt < 8; ++nt)
                    mma16816(acc[mt][nt], a[mt], b[nt]);
        }
    }

    // ------------------------------ epilogue --------------------------------
    const float* bsm = (const float*)smem;
    const int lq = lid >> 2;
    const int lr = lid & 3;

#pragma unroll
    for (int mt = 0; mt < 2; ++mt) {
#pragma unroll
        for (int hf = 0; hf < 2; ++hf) {
            const int m = m0 + wm * 32 + mt * 16 + lq + hf * 8;
#pragma unroll
            for (int nt = 0; nt < 8; ++nt) {
                const int n = n0 + wn * 64 + nt * 8 + lr * 2;
                float x0 = acc[mt][nt][hf * 2 + 0] + bsm[n - n0];
                float x1 = acc[mt][nt][hf * 2 + 1] + bsm[n - n0 + 1];
                if (DO_TANH) { x0 = tfast(x0); x1 = tfast(x1); }

                if (TRANS) {
                    const int s = m & 4095, bb = m >> 12;
                    float* dst = outF + ((size_t)(s * 8 + bb)) * HD + n;
                    *(float2*)dst = make_float2(x0, x1);
                } else {
                    __half2 hh;
                    hh.x = __float2half_rn(x0);
                    hh.y = __float2half_rn(x1);
                    *(__half2*)(outA + (size_t)m * HD + n) = hh;
                }
                if (HSF && ((m & 4095) == 4095)) {
                    float* hd = hsf + (size_t)(m >> 12) * HD + n;
                    *(float2*)hd = make_float2(x0, x1);
                }
            }
        }
    }
}

// --------------------------- fused prep kernel -------------------------------
//   blocks [0,128)      : Weff = Whh + Wxh@Why -> fp16 plane (slots 1,2)
//   blocks [128,256)    : beff = bhh + bxh + Wxh@bhy (warp reductions)
//   blocks [256,2304)   : convert X -> g_X (fp16)
//   blocks [2304,2368)  : convert W_xh0 / final projection -> fp16 (slots 0,3)
struct PrepP {
    const float* Wxh[2];
    const float* Why[2];
    const float* Whh[2];
    fp16*        WeffC[2];
    const float* bhh[2];
    const float* bxh[2];
    const float* bhy[2];
    float*       beff[2];
    const float* xs;
    fp16*        X;
    const float* Wraw[2];
    fp16*        Wbase;
};

__device__ void prep_weff(const PrepP& p, int id, int t)
{
    const int l  = id >> 6;
    const int rm = id & 63;
    const int m0 = (rm >> 3) * 64;
    const int n0 = (rm & 7) * 64;
    const float* __restrict__ A = p.Wxh[l];
    const float* __restrict__ B = p.Why[l];
    const float* __restrict__ Wadd = p.Whh[l];
    fp16* __restrict__ C = p.WeffC[l];

    __shared__ float As[16][64];
    __shared__ float Bs[16][64];
    const int tx = t & 15, ty = t >> 4;

    float acc[4][4] = {};
#pragma unroll 1
    for (int kt = 0; kt < 512; kt += 16) {
#pragma unroll
        for (int e = t; e < 1024; e += 256) {
            int am = e >> 4, ak = e & 15;
            As[ak][am] = A[(size_t)(m0 + am) * 512 + kt + ak];
            int bj = e & 63, bk = e >> 6;
            Bs[bk][bj] = B[(size_t)(kt + bk) * 512 + n0 + bj];
        }
        __syncthreads();
#pragma unroll
        for (int k = 0; k < 16; ++k) {
            float af[4], bf[4];
#pragma unroll
            for (int i = 0; i < 4; ++i) af[i] = As[k][ty * 4 + i];
#pragma unroll
            for (int j = 0; j < 4; ++j) bf[j] = Bs[k][tx * 4 + j];
#pragma unroll
            for (int i = 0; i < 4; ++i)
#pragma unroll
                for (int j = 0; j < 4; ++j)
                    acc[i][j] = fmaf(af[i], bf[j], acc[i][j]);
        }
        __syncthreads();
    }

    const int kcol = n0 + tx * 4;
#pragma unroll
    for (int i = 0; i < 4; ++i) {
        const int n = m0 + ty * 4 + i;
        fp16 h4[4];
#pragma unroll
        for (int j = 0; j < 4; ++j)
            h4[j] = __float2half_rn(Wadd[(size_t)n * 512 + kcol + j] + acc[i][j]);
        *(uint2*)(C + (size_t)n * 512 + kcol) = *(uint2*)h4;
    }
}

__device__ void prep_beff(const PrepP& p, int id, int t)
{
    const int gw = id * 8 + (t >> 5);
    const int l = gw >> 9;
    const int n = gw & 511;
    const int lane = t & 31;
    const float* W  = p.Wxh[l] + (size_t)n * 512 + lane * 16;
    const float* bh = p.bhy[l] + lane * 16;
    float s = 0.0f;
#pragma unroll
    for (int k = 0; k < 16; k += 4) {
        float4 w = *(const float4*)(W + k);
        float4 b = *(const float4*)(bh + k);
        s = fmaf(w.x, b.x, s); s = fmaf(w.y, b.y, s);
        s = fmaf(w.z, b.z, s); s = fmaf(w.w, b.w, s);
    }
#pragma unroll
    for (int o = 16; o; o >>= 1) s += __shfl_xor_sync(0xFFFFFFFFu, s, o);
    if (lane == 0) p.beff[l][n] = p.bhh[l][n] + p.bxh[l][n] + s;
}

__device__ void prep_cvt(const float* __restrict__ src0, fp16* __restrict__ d)
{
    uint32_t h[16];
#pragma unroll
    for (int j = 0; j < 8; ++j) {
        float4 v = *(const float4*)(src0 + j * 4);
        __half2 h0, h1;
        h0.x = __float2half_rn(v.x); h0.y = __float2half_rn(v.y);
        h1.x = __float2half_rn(v.z); h1.y = __float2half_rn(v.w);
        h[2*j] = *(uint32_t*)&h0; h[2*j+1] = *(uint32_t*)&h1;
    }
#pragma unroll
    for (int j = 0; j < 4; ++j)
        ((uint4*)d)[j] = *(uint4*)(h + 4*j);
}

__global__ void __launch_bounds__(256) k_prep(PrepP p)
{
    const int bid = blockIdx.x;
    const int t   = threadIdx.x;

    if (bid < 128) {
        prep_weff(p, bid, t);
    } else if (bid < 256) {
        prep_beff(p, bid - 128, t);
    } else if (bid < 2304) {
        const size_t off = ((size_t)(bid - 256) * 256 + t) * 32;
        prep_cvt(p.xs + off, p.X + off);
    } else {
        const size_t idx = (size_t)(bid - 2304) * 256 + t;
        const int slot = (int)(idx >> 13);           // 0 or 1
        const size_t off = (idx & 8191) * 32;
        // slot 0 -> W slot 0 (W_xh0), slot 1 -> W slot 3 (final projection)
        prep_cvt(p.Wraw[slot] + off,
                 p.Wbase + (size_t)(slot * 3) * WELEMS + off);
    }
}

// --------------------------------- launcher ---------------------------------
extern "C" void kernel_launch(void* const* d_in, const int* in_sizes, int n_in,
                              void* d_out, int out_size)
{
    const float* xs     = (const float*)d_in[0];
    const float* W_xh0  = (const float*)d_in[1];
    const float* b_xh0  = (const float*)d_in[2];
    const float* b_hh0  = (const float*)d_in[4];
    const float* W_hy0  = (const float*)d_in[5];
    const float* b_hy0  = (const float*)d_in[6];
    const float* W_xh_h = (const float*)d_in[7];
    const float* b_xh_h = (const float*)d_in[8];
    const float* W_hh_h = (const float*)d_in[9];
    const float* b_hh_h = (const float*)d_in[10];
    const float* W_hy_h = (const float*)d_in[11];
    const float* b_hy_h = (const float*)d_in[12];

    float* out = (float*)d_out;
    float* hs_final = out + (size_t)4096 * 8 * HD;

    fp16 *X, *H0, *H1, *Wb;
    float *beff;
    cudaGetSymbolAddress((void**)&X,   g_X);
    cudaGetSymbolAddress((void**)&H0,  g_H0);
    cudaGetSymbolAddress((void**)&H1,  g_H1);
    cudaGetSymbolAddress((void**)&Wb,  g_W);
    cudaGetSymbolAddress((void**)&beff, g_beff);

    cudaFuncSetAttribute(gemm_stage<true,  false, false>,
                         cudaFuncAttributeMaxDynamicSharedMemorySize, SMEMB);
    cudaFuncSetAttribute(gemm_stage<true,  true,  false>,
                         cudaFuncAttributeMaxDynamicSharedMemorySize, SMEMB);
    cudaFuncSetAttribute(gemm_stage<false, false, true >,
                         cudaFuncAttributeMaxDynamicSharedMemorySize, SMEMB);

#define WS(s) (Wb + (size_t)(s) * WELEMS)

    // ---- fused prep ----
    PrepP pp;
    pp.Wxh[0] = W_xh_h;      pp.Wxh[1] = W_xh_h + WSZ;
    pp.Why[0] = W_hy0;       pp.Why[1] = W_hy_h;
    pp.Whh[0] = W_hh_h;      pp.Whh[1] = W_hh_h + WSZ;
    pp.WeffC[0] = WS(1);     pp.WeffC[1] = WS(2);
    pp.bhh[0] = b_hh_h;      pp.bhh[1] = b_hh_h + HD;
    pp.bxh[0] = b_xh_h;      pp.bxh[1] = b_xh_h + HD;
    pp.bhy[0] = b_hy0;       pp.bhy[1] = b_hy_h;
    pp.beff[0] = beff;       pp.beff[1] = beff + HD;
    pp.xs = xs;
    pp.X  = X;
    pp.Wraw[0] = W_xh0;
    pp.Wraw[1] = W_hy_h + WSZ;
    pp.Wbase = Wb;
    k_prep<<<2368, 256>>>(pp);

    dim3 grid(HD / BN, MROWS / BM);   // (4, 256) = 1024 CTAs
    dim3 block(NTH);

    // 1) h0 = tanh(X @ W_xh0^T + b_xh0 + b_hh0)
    gemm_stage<true, false, false><<<grid, block, SMEMB>>>(
        X, WS(0), b_xh0, b_hh0, H0, nullptr, nullptr);
    // 2) h1 = tanh(h0 @ Weff0^T + beff0)
    gemm_stage<true, false, false><<<grid, block, SMEMB>>>(
        H0, WS(1), beff, nullptr, H1, nullptr, nullptr);
    // 3) h2 = tanh(h1 @ Weff1^T + beff1)  (+ hs_final)
    gemm_stage<true, true, false><<<grid, block, SMEMB>>>(
        H1, WS(2), beff + HD, nullptr, H0, nullptr, hs_final);
    // 4) outputs = (h2 @ W_hy_h[1]^T + b_hy_h[1]) -> [S, B, H] fp32
    gemm_stage<false, false, true><<<grid, block, SMEMB>>>(
        H0, WS(3), b_hy_h + HD, nullptr, nullptr, out, nullptr);
#undef WS
}